// round 16
// baseline (speedup 1.0000x reference)
#include <cuda_runtime.h>
#include <cuda_bf16.h>

#define NSAMPLE 32
#define MAXN 8192
#define RADIUS2 1.0f
#define MAXCH 8   // max 32-lane chunks of K supported by the batched path (K<=256)
#define MAX_FUSED_BLOCKS 576   // co-residency bound: 148 SMs * 4 blocks/SM (margin)

// Scratch (no allocations allowed)
__device__ int   g_ball[MAXN * NSAMPLE];       // fallback path only
__device__ float g_delta[MAXN * NSAMPLE * 3];  // fallback path only
__device__ int   g_cnt[MAXN];
__device__ int   g_off[MAXN + 1];
__device__ int   g_done  = 0;
__device__ int   g_done2 = 0;
__device__ int   g_flag  = 0;

// sum of squares with explicit mul-then-left-assoc-add (no fma contraction),
// matching XLA's elementwise square + axis reduce.
__device__ __forceinline__ float sq3(float ax, float ay, float az) {
    return __fadd_rn(__fadd_rn(__fmul_rn(ax, ax), __fmul_rn(ay, ay)), __fmul_rn(az, az));
}

// ---------------------------------------------------------------------------
// FUSED kernel (C==32, W=35): query -> grid barrier (co-resident) -> scan ->
// in-register gather + row-owned tail zero. One warp per point, 8 warps/block.
// ---------------------------------------------------------------------------
__global__ void __launch_bounds__(256, 4) fused35_kernel(
        const float* __restrict__ xyz,
        const float* __restrict__ new_xyz,
        const float* __restrict__ rois,
        const float* __restrict__ feat,
        float* __restrict__ out_group,
        float* __restrict__ out_idx,
        int N, int Nb, int M, int K, int L, int has_idx) {
    const int W = 35, C = 32;
    int lane = threadIdx.x & 31;
    int wid  = threadIdx.x >> 5;
    int tid  = threadIdx.x;
    int n    = blockIdx.x * 8 + wid;
    int gw   = n;

    __shared__ int   s_gi[8][33];
    __shared__ float s_dx[8][33], s_dy[8][33], s_dz[8][33];
    __shared__ int   sh_isLast;
    __shared__ int   wsum[8];

    // ======================= phase 1: query =======================
    int count = 0;
    float fv = 0.f;
    if (n < N) {
        int b = n / Nb;
        float px = xyz[3 * n + 0], py = xyz[3 * n + 1], pz = xyz[3 * n + 2];
        fv = __ldg(&feat[(size_t)n * C + lane]);      // prefetch (pre-barrier)

        // roi membership bitmask via per-lane checks + ballot
        const float* r = rois + (size_t)b * M * 7;
        unsigned long long bm = 0ull;
        for (int mb = 0; mb < M; mb += 32) {
            int m = mb + lane;
            bool in = false;
            if (m < M) {
                float cx = r[m * 7 + 0], cy = r[m * 7 + 1], cz = r[m * 7 + 2];
                float dx = r[m * 7 + 3], dy = r[m * 7 + 4], dz = r[m * 7 + 5];
                float r2 = sq3(dx, dy, dz);
                float d2 = sq3(__fsub_rn(px, cx), __fsub_rn(py, cy), __fsub_rn(pz, cz));
                in = (d2 <= r2);
            }
            unsigned bits = __ballot_sync(0xffffffffu, in);
            bm |= ((unsigned long long)bits) << mb;
        }

        // ordered ball query: first NSAMPLE hits in j = m*K + k order
        int baseMK = b * M * K;
        int nch = (K + 31) >> 5;
        while (bm && count < NSAMPLE) {
            int m = __ffsll((long long)bm) - 1;
            bm &= bm - 1ull;
            const float* g = new_xyz + ((size_t)(b * M + m)) * K * 3;

            // batch-load ALL grid points for this roi (high MLP)
            float gx[MAXCH], gy[MAXCH], gz[MAXCH];
            #pragma unroll
            for (int j = 0; j < MAXCH; j++) {
                if (j < nch) {
                    int k = (j << 5) + lane;
                    int kc = k < K ? k : K - 1;           // clamp (masked later)
                    gx[j] = __ldg(&g[3 * kc + 0]);
                    gy[j] = __ldg(&g[3 * kc + 1]);
                    gz[j] = __ldg(&g[3 * kc + 2]);
                }
            }
            #pragma unroll
            for (int j = 0; j < MAXCH; j++) {
                if (j < nch && count < NSAMPLE) {
                    int k = (j << 5) + lane;
                    bool ok = false;
                    float ddx = 0.f, ddy = 0.f, ddz = 0.f;
                    if (k < K) {
                        ddx = __fsub_rn(px, gx[j]);
                        ddy = __fsub_rn(py, gy[j]);
                        ddz = __fsub_rn(pz, gz[j]);
                        float d2 = sq3(ddx, ddy, ddz);
                        ok = (d2 <= RADIUS2);
                    }
                    unsigned bits = __ballot_sync(0xffffffffu, ok);
                    int rank = count + __popc(bits & ((1u << lane) - 1u));
                    if (ok && rank < NSAMPLE) {
                        s_gi[wid][rank] = baseMK + m * K + k;
                        s_dx[wid][rank] = ddx;
                        s_dy[wid][rank] = ddy;
                        s_dz[wid][rank] = ddz;
                    }
                    count += __popc(bits);
                }
            }
        }
        if (count > NSAMPLE) count = NSAMPLE;
        if (lane == 0) g_cnt[n] = count;
    }

    // ======================= rendezvous: arrive =======================
    __threadfence();
    __syncthreads();
    if (tid == 0) {
        int t = atomicAdd(&g_done, 1);
        sh_isLast = (t == (int)gridDim.x - 1) ? 1 : 0;
    }
    __syncthreads();

    // last block: exclusive scan of g_cnt -> g_off, then release flag
    if (sh_isLast) {
        int per = (N + 255) / 256;           // <= 32 for MAXN=8192
        int base = tid * per;
        int loc[32];
        int s = 0;
        #pragma unroll 4
        for (int i = 0; i < per; i++) {
            int v = (base + i < N) ? __ldcg(&g_cnt[base + i]) : 0;
            loc[i] = v;
            s += v;
        }
        int pre = s;
        #pragma unroll
        for (int d = 1; d < 32; d <<= 1) {
            int t = __shfl_up_sync(0xffffffffu, pre, d);
            if (lane >= d) pre += t;
        }
        if (lane == 31) wsum[wid] = pre;
        __syncthreads();
        if (tid == 0) {
            int acc = 0;
            #pragma unroll
            for (int w = 0; w < 8; w++) { int t = wsum[w]; wsum[w] = acc; acc += t; }
        }
        __syncthreads();
        int run = wsum[wid] + (pre - s);
        #pragma unroll 4
        for (int i = 0; i < per; i++) {
            if (base + i < N) g_off[base + i] = run;
            run += loc[i];
        }
        if (tid == 255) g_off[N] = run;
        __threadfence();
        __syncthreads();
        if (tid == 0) atomicExch(&g_flag, 1);   // release
    }

    // all blocks: wait for scan (volatile poll, nanosleep backoff)
    if (tid == 0) {
        while (((volatile int*)&g_flag)[0] == 0) { __nanosleep(64); }
    }
    __syncthreads();
    __threadfence();   // acquire: g_off reads below see the scan

    // ======================= phase 2: gather + tail zero =======================
    int total = __ldcg(&g_off[N]);

    if (n < N && count > 0) {
        int off = __ldcg(&g_off[n]);
        float* base = out_group + (size_t)off * W;
        // feature block: one coalesced store per row, lane-resident value
        float* p = base + 3 + lane;
        #pragma unroll 4
        for (int s = 0; s < count; s++) {
            *p = fv;
            p += W;
        }
        // residual fixup: lane s writes its row's xyz deltas + idx (from smem)
        if (lane < count) {
            float* rr = base + lane * W;
            rr[0] = s_dx[wid][lane];
            rr[1] = s_dy[wid][lane];
            rr[2] = s_dz[wid][lane];
            if (has_idx) out_idx[off + lane] = (float)s_gi[wid][lane];
        }
    }

    // tail zero: warp gw owns output rows [gw*32, (gw+1)*32)
    if (n < N) {
        int r0 = gw * 32, r1 = r0 + 32;
        if (r1 > total) {
            int z0 = r0 > total ? r0 : total;
            if (z0 == r0) {
                // fully-tail warp: flat float4 zero of 32 rows * 35 floats
                float4 z4 = make_float4(0.f, 0.f, 0.f, 0.f);
                float4* o4 = (float4*)(out_group + (size_t)r0 * W);
                #pragma unroll
                for (int i = lane; i < 280; i += 32) o4[i] = z4;
            } else {
                // boundary warp: scalar per-row zero
                for (int rr = z0; rr < r1; rr++) {
                    float* row = out_group + (size_t)rr * W;
                    for (int c = lane; c < W; c += 32) row[c] = 0.f;
                }
            }
            if (has_idx) {
                int rr = r0 + lane;
                if (rr >= total && rr < L) out_idx[rr] = 0.f;
            }
        }
    }

    // ======================= rendezvous reset (for graph replay) ==========
    __threadfence();
    __syncthreads();
    if (tid == 0) {
        int t = atomicAdd(&g_done2, 1);
        if (t == (int)gridDim.x - 1) { g_done = 0; g_done2 = 0; g_flag = 0; }
    }
}

// ---------------------------------------------------------------------------
// FALLBACK PATH (C != 32 or too many blocks for co-residency): the proven
// R14 two-kernel pipeline.
// ---------------------------------------------------------------------------
__global__ void __launch_bounds__(256) query_zero_scan_kernel(
        const float* __restrict__ xyz,
        const float* __restrict__ new_xyz,
        const float* __restrict__ rois,
        float* __restrict__ out,
        int out_total,
        int N, int Nb, int M, int K) {
    int lane = threadIdx.x & 31;
    int wid  = threadIdx.x >> 5;
    int n    = blockIdx.x * 8 + wid;
    int gw   = n;
    int nwarps = gridDim.x * 8;

    if (n < N) {
        int b = n / Nb;
        float px = xyz[3 * n + 0], py = xyz[3 * n + 1], pz = xyz[3 * n + 2];

        const float* r = rois + (size_t)b * M * 7;
        unsigned long long bm = 0ull;
        for (int mb = 0; mb < M; mb += 32) {
            int m = mb + lane;
            bool in = false;
            if (m < M) {
                float cx = r[m * 7 + 0], cy = r[m * 7 + 1], cz = r[m * 7 + 2];
                float dx = r[m * 7 + 3], dy = r[m * 7 + 4], dz = r[m * 7 + 5];
                float r2 = sq3(dx, dy, dz);
                float d2 = sq3(__fsub_rn(px, cx), __fsub_rn(py, cy), __fsub_rn(pz, cz));
                in = (d2 <= r2);
            }
            unsigned bits = __ballot_sync(0xffffffffu, in);
            bm |= ((unsigned long long)bits) << mb;
        }

        int count = 0;
        int* outp = g_ball + n * NSAMPLE;
        float* dlp = g_delta + (size_t)n * NSAMPLE * 3;
        int baseMK = b * M * K;
        while (bm && count < NSAMPLE) {
            int m = __ffsll((long long)bm) - 1;
            bm &= bm - 1ull;
            const float* g = new_xyz + ((size_t)(b * M + m)) * K * 3;
            for (int k0 = 0; k0 < K && count < NSAMPLE; k0 += 32) {
                int k = k0 + lane;
                bool ok = false;
                float ddx = 0.f, ddy = 0.f, ddz = 0.f;
                if (k < K) {
                    ddx = __fsub_rn(px, g[3 * k + 0]);
                    ddy = __fsub_rn(py, g[3 * k + 1]);
                    ddz = __fsub_rn(pz, g[3 * k + 2]);
                    float d2 = sq3(ddx, ddy, ddz);
                    ok = (d2 <= RADIUS2);
                }
                unsigned bits = __ballot_sync(0xffffffffu, ok);
                int rank = count + __popc(bits & ((1u << lane) - 1u));
                if (ok && rank < NSAMPLE) {
                    outp[rank] = baseMK + m * K + k;
                    float* dp = dlp + rank * 3;
                    dp[0] = ddx; dp[1] = ddy; dp[2] = ddz;
                }
                count += __popc(bits);
            }
        }
        if (lane == 0) g_cnt[n] = count < NSAMPLE ? count : NSAMPLE;
    }

    {   // absorbed zero
        float4 z4 = make_float4(0.f, 0.f, 0.f, 0.f);
        float4* o4 = (float4*)out;
        int n4 = out_total >> 2;
        int t = gw * 32 + lane;
        int stride = nwarps * 32;
        for (int i = t; i < n4; i += stride) o4[i] = z4;
        if (gw == 0) {
            int rem = out_total & 3;
            if (lane < rem) out[(n4 << 2) + lane] = 0.f;
        }
    }

    __threadfence();
    __shared__ int sh_isLast;
    __syncthreads();
    if (threadIdx.x == 0) {
        int t = atomicAdd(&g_done, 1);
        sh_isLast = (t == (int)gridDim.x - 1) ? 1 : 0;
    }
    __syncthreads();
    if (!sh_isLast) return;

    int tid = threadIdx.x;
    int per = (N + 255) / 256;
    int base = tid * per;
    int loc[32];
    int s = 0;
    #pragma unroll 4
    for (int i = 0; i < per; i++) {
        int v = (base + i < N) ? __ldcg(&g_cnt[base + i]) : 0;
        loc[i] = v;
        s += v;
    }
    int pre = s;
    #pragma unroll
    for (int d = 1; d < 32; d <<= 1) {
        int t = __shfl_up_sync(0xffffffffu, pre, d);
        if (lane >= d) pre += t;
    }
    __shared__ int wsum[8];
    if (lane == 31) wsum[wid] = pre;
    __syncthreads();
    if (tid == 0) {
        int acc = 0;
        #pragma unroll
        for (int w = 0; w < 8; w++) { int t = wsum[w]; wsum[w] = acc; acc += t; }
    }
    __syncthreads();
    int run = wsum[wid] + (pre - s);
    #pragma unroll 4
    for (int i = 0; i < per; i++) {
        if (base + i < N) g_off[base + i] = run;
        run += loc[i];
    }
    if (tid == 255) g_off[N] = run;
    if (tid == 0) g_done = 0;
}

__global__ void __launch_bounds__(256) gather_generic_kernel(
        const float* __restrict__ xyz,
        const float* __restrict__ new_xyz,
        const float* __restrict__ feat,
        float* __restrict__ out_group,
        float* __restrict__ out_idx,
        int N, int C, int has_idx) {
    int gw   = (blockIdx.x * blockDim.x + threadIdx.x) >> 5;
    int lane = threadIdx.x & 31;
    int L = N * NSAMPLE;
    if (gw >= L) return;
    int W = 3 + C;

    int n = gw >> 5;
    int s = gw & (NSAMPLE - 1);
    if (s < g_cnt[n]) {
        int pos = g_off[n] + s;
        int gi  = g_ball[n * NSAMPLE + s];
        float* row = out_group + (size_t)pos * W;
        for (int c = lane; c < W; c += 32) {
            float v;
            if (c < 3) v = __fsub_rn(xyz[3 * n + c], new_xyz[3 * (size_t)gi + c]);
            else       v = feat[(size_t)n * C + (c - 3)];
            row[c] = v;
        }
        if (lane == 0 && has_idx) out_idx[pos] = (float)gi;
    }
}

// ---------------------------------------------------------------------------
extern "C" void kernel_launch(void* const* d_in, const int* in_sizes, int n_in,
                              void* d_out, int out_size) {
    const float* xyz      = (const float*)d_in[0];
    const float* new_xyz  = (const float*)d_in[2];
    const float* rois     = (const float*)d_in[3];
    const float* features = (const float*)d_in[4];

    int N  = in_sizes[0] / 3;
    int B  = in_sizes[1];
    int M  = in_sizes[3] / (7 * B);
    int K  = in_sizes[2] / (3 * B * M);
    int C  = in_sizes[4] / N;
    int Nb = N / B;
    int L  = N * NSAMPLE;
    int W  = 3 + C;

    float* out = (float*)d_out;
    int has_idx = (out_size >= L * W + L) ? 1 : 0;
    float* out_idx = out + (size_t)L * W;

    int blocks = (N + 7) / 8;
    int nch = (K + 31) >> 5;

    if (C == 32 && nch <= MAXCH && blocks <= MAX_FUSED_BLOCKS) {
        // single fused kernel: query -> grid barrier -> scan -> gather + zero
        fused35_kernel<<<blocks, 256>>>(xyz, new_xyz, rois, features,
                                        out, out_idx, N, Nb, M, K, L, has_idx);
    } else {
        query_zero_scan_kernel<<<blocks, 256>>>(
            xyz, new_xyz, rois, out, out_size, N, Nb, M, K);
        int gblocks = (L * 32 + 255) / 256;
        gather_generic_kernel<<<gblocks, 256>>>(xyz, new_xyz, features, out, out_idx,
                                                N, C, has_idx);
    }
}